// round 1
// baseline (speedup 1.0000x reference)
#include <cuda_runtime.h>
#include <math.h>

typedef unsigned long long u64;

#define HEADS 8
#define DH    64
#define NDIM  256
#define INNER 512
#define NTOKS 4096
#define BATCH 8

// ---------------- scratch (device globals: allocation-guard safe) ----------------
__device__ float g_kv  [(size_t)BATCH * NTOKS * 1024];   // 134 MB: [b, t, (k0..k7,v0..v7) 1024]
__device__ float g_q   [(size_t)BATCH * NTOKS * INNER];  // 67 MB:  [b, t, h*64+d]
__device__ float g_dotp[(size_t)64 * 8 * DH * DH];       // 8.4 MB: [bh, split, d*64+e]
__device__ float g_w2  [(size_t)BATCH * INNER * NDIM];   // 4 MB:   [b, h*64+d, c]

// ---------------- f32x2 packed helpers (sm_103a) ----------------
__device__ __forceinline__ u64 pack2(float x, float y) {
    u64 r; asm("mov.b64 %0, {%1,%2};" : "=l"(r) : "f"(x), "f"(y)); return r;
}
__device__ __forceinline__ u64 ffma2(u64 a, u64 b, u64 c) {
    u64 d; asm("fma.rn.f32x2 %0, %1, %2, %3;" : "=l"(d) : "l"(a), "l"(b), "l"(c)); return d;
}
__device__ __forceinline__ void unpack2(u64 v, float& x, float& y) {
    asm("mov.b64 {%0,%1}, %2;" : "=f"(x), "=f"(y) : "l"(v));
}

// ---------------- generic 128x128x8 SGEMM, f32x2 inner loop ----------------
// C[M,N] = A[M,K] @ B[K,N] (+bias), row-major, all tile dims divide exactly.
__global__ __launch_bounds__(256, 2) void sgemm128(
    const float* __restrict__ A, const float* __restrict__ B, float* __restrict__ C,
    int M, int N, int K, long sA, long sB, long sC, const float* __restrict__ bias)
{
    A += (long)blockIdx.z * sA;
    B += (long)blockIdx.z * sB;
    C += (long)blockIdx.z * sC;
    const int m0 = blockIdx.y * 128, n0 = blockIdx.x * 128;
    const int tid = threadIdx.x;
    const int ty = tid >> 4, tx = tid & 15;

    __shared__ float As[8][132];
    __shared__ float Bs[8][128];

    const int arow = tid >> 1, acol = (tid & 1) * 4;
    const int brow = tid >> 5, bcol = (tid & 31) * 4;

    const float* gA = A + (long)(m0 + arow) * K + acol;
    const float* gB = B + (long)brow * N + n0 + bcol;

    u64 acc[8][4];
    #pragma unroll
    for (int i = 0; i < 8; i++)
        #pragma unroll
        for (int j = 0; j < 4; j++) acc[i][j] = 0ull;

    const int nt = K >> 3;
    float4 pa = *(const float4*)gA;
    float4 pb = *(const float4*)gB;

    for (int t = 0; t < nt; t++) {
        As[acol + 0][arow] = pa.x;
        As[acol + 1][arow] = pa.y;
        As[acol + 2][arow] = pa.z;
        As[acol + 3][arow] = pa.w;
        *(float4*)&Bs[brow][bcol] = pb;
        __syncthreads();
        if (t + 1 < nt) {
            pa = *(const float4*)(gA + (long)(t + 1) * 8);
            pb = *(const float4*)(gB + (long)(t + 1) * 8 * N);
        }
        #pragma unroll
        for (int k = 0; k < 8; k++) {
            float4 a0 = *(const float4*)&As[k][ty * 8];
            float4 a1 = *(const float4*)&As[k][ty * 8 + 4];
            const u64* bp = (const u64*)&Bs[k][tx * 8];
            u64 b0 = bp[0], b1 = bp[1], b2 = bp[2], b3 = bp[3];
            float av[8] = {a0.x, a0.y, a0.z, a0.w, a1.x, a1.y, a1.z, a1.w};
            #pragma unroll
            for (int i = 0; i < 8; i++) {
                u64 ap = pack2(av[i], av[i]);
                acc[i][0] = ffma2(ap, b0, acc[i][0]);
                acc[i][1] = ffma2(ap, b1, acc[i][1]);
                acc[i][2] = ffma2(ap, b2, acc[i][2]);
                acc[i][3] = ffma2(ap, b3, acc[i][3]);
            }
        }
        __syncthreads();
    }

    float bv[8];
    #pragma unroll
    for (int c = 0; c < 8; c++) bv[c] = 0.f;
    if (bias) {
        #pragma unroll
        for (int c = 0; c < 8; c++) bv[c] = bias[n0 + tx * 8 + c];
    }
    #pragma unroll
    for (int i = 0; i < 8; i++) {
        float o[8];
        #pragma unroll
        for (int j = 0; j < 4; j++) unpack2(acc[i][j], o[2 * j], o[2 * j + 1]);
        #pragma unroll
        for (int c = 0; c < 8; c++) o[c] += bv[c];
        const long row = m0 + ty * 8 + i;
        *(float4*)&C[row * N + n0 + tx * 8]     = make_float4(o[0], o[1], o[2], o[3]);
        *(float4*)&C[row * N + n0 + tx * 8 + 4] = make_float4(o[4], o[5], o[6], o[7]);
    }
}

// ---------------- rotary helper ----------------
// lane l of a warp holds head-dims d=l and d=32+l. Pairs are (j, j+16) within
// each 32-wide half; angle index j = l & 15 (x-half angle for d<32, y-half for d>=32).
__device__ __forceinline__ void warp_rot(float& v0, float& v1, int l, float px, float py) {
    const int j = l & 15;
    const float invf = exp2f(-(float)j * (13.287712379549449f / 16.f)); // 10000^(-j/16)
    float sx, cx, sy, cy;
    sincosf(px * invf, &sx, &cx);
    sincosf(py * invf, &sy, &cy);
    float p0 = __shfl_xor_sync(0xffffffffu, v0, 16);
    float p1 = __shfl_xor_sync(0xffffffffu, v1, 16);
    if (l < 16) { v0 = v0 * cx - p0 * sx; v1 = v1 * cy - p1 * sy; }
    else        { v0 = v0 * cx + p0 * sx; v1 = v1 * cy + p1 * sy; }
}

__device__ __forceinline__ float warp_sum(float s) {
    #pragma unroll
    for (int o = 16; o; o >>= 1) s += __shfl_xor_sync(0xffffffffu, s, o);
    return s;
}

// ---------------- instance-norm + rotary on kv (in place) ----------------
__global__ void normrot_kv(float* __restrict__ kv, const float* __restrict__ z_pos) {
    const int tok = blockIdx.x;                 // b*4096 + t
    const int w = threadIdx.x >> 5;             // head
    const int l = threadIdx.x & 31;
    float* kb = kv + (size_t)tok * 1024 + w * 64;
    float* vb = kb + 512;
    const float px = z_pos[tok * 2 + 0] * 64.f;
    const float py = z_pos[tok * 2 + 1] * 64.f;

    // k: norm + rotary
    float k0 = kb[l], k1 = kb[l + 32];
    float mu = warp_sum(k0 + k1) * (1.f / 64.f);
    float d0 = k0 - mu, d1 = k1 - mu;
    float var = warp_sum(d0 * d0 + d1 * d1) * (1.f / 64.f);
    float inv = rsqrtf(var + 1e-5f);
    d0 *= inv; d1 *= inv;
    warp_rot(d0, d1, l, px, py);
    kb[l] = d0; kb[l + 32] = d1;

    // v: norm only
    float u0 = vb[l], u1 = vb[l + 32];
    float muv = warp_sum(u0 + u1) * (1.f / 64.f);
    float e0 = u0 - muv, e1 = u1 - muv;
    float varv = warp_sum(e0 * e0 + e1 * e1) * (1.f / 64.f);
    float invv = rsqrtf(varv + 1e-5f);
    vb[l] = e0 * invv; vb[l + 32] = e1 * invv;
}

// ---------------- rotary on q (in place) ----------------
__global__ void rot_q(float* __restrict__ q, const float* __restrict__ x_pos) {
    const int tok = blockIdx.x;
    const int w = threadIdx.x >> 5;
    const int l = threadIdx.x & 31;
    float* base = q + (size_t)tok * 512 + w * 64;
    const float px = x_pos[tok * 2 + 0] * 64.f;
    const float py = x_pos[tok * 2 + 1] * 64.f;
    float v0 = base[l], v1 = base[l + 32];
    warp_rot(v0, v1, l, px, py);
    base[l] = v0; base[l + 32] = v1;
}

// ---------------- split-K Gram: dots_part[bh, split] = sum_t k[t,:]^T v[t,:] ----------------
__global__ __launch_bounds__(256) void dots_part(const float* __restrict__ kv, float* __restrict__ part) {
    const int split = blockIdx.x;   // 0..7
    const int bh = blockIdx.y;      // 0..63
    const int b = bh >> 3, h = bh & 7;
    __shared__ float ks[64][64];
    __shared__ float vs[64][64];
    const int tid = threadIdx.x;
    const int ty = tid >> 4, tx = tid & 15;
    float acc[4][4] = {};
    const float* kvb = kv + (size_t)b * NTOKS * 1024;

    for (int c = 0; c < 8; c++) {
        const int t0 = split * 512 + c * 64;
        #pragma unroll
        for (int r = 0; r < 8; r++) {
            int f = r * 256 + tid;
            int token = f >> 5;
            int isv = (f >> 4) & 1;
            int col4 = f & 15;
            float4 val = *(const float4*)&kvb[(size_t)(t0 + token) * 1024 + isv * 512 + h * 64 + col4 * 4];
            float* dst = isv ? &vs[token][col4 * 4] : &ks[token][col4 * 4];
            *(float4*)dst = val;
        }
        __syncthreads();
        #pragma unroll 4
        for (int t = 0; t < 64; t++) {
            float4 a = *(const float4*)&ks[t][ty * 4];
            float4 v = *(const float4*)&vs[t][tx * 4];
            acc[0][0] += a.x * v.x; acc[0][1] += a.x * v.y; acc[0][2] += a.x * v.z; acc[0][3] += a.x * v.w;
            acc[1][0] += a.y * v.x; acc[1][1] += a.y * v.y; acc[1][2] += a.y * v.z; acc[1][3] += a.y * v.w;
            acc[2][0] += a.z * v.x; acc[2][1] += a.z * v.y; acc[2][2] += a.z * v.z; acc[2][3] += a.z * v.w;
            acc[3][0] += a.w * v.x; acc[3][1] += a.w * v.y; acc[3][2] += a.w * v.z; acc[3][3] += a.w * v.w;
        }
        __syncthreads();
    }
    float* dst = part + ((size_t)bh * 8 + split) * 4096;
    #pragma unroll
    for (int i = 0; i < 4; i++)
        *(float4*)&dst[(ty * 4 + i) * 64 + tx * 4] = make_float4(acc[i][0], acc[i][1], acc[i][2], acc[i][3]);
}

// ---------------- W2[b, h*64+d, c] = (sum_splits dots)/n2 @ Wout[h*64+e, c] ----------------
__global__ __launch_bounds__(256) void w2k(const float* __restrict__ part, const float* __restrict__ Wout,
                                           float* __restrict__ W2) {
    const int bh = blockIdx.x;
    const int b = bh >> 3, h = bh & 7;
    __shared__ float ds[4096];
    const int tid = threadIdx.x;
    #pragma unroll
    for (int j = 0; j < 16; j++) {
        int idx = j * 256 + tid;
        float s = 0.f;
        #pragma unroll
        for (int sp = 0; sp < 8; sp++) s += part[((size_t)bh * 8 + sp) * 4096 + idx];
        ds[idx] = s * (1.f / 4096.f);
    }
    __syncthreads();

    float acc[64];
    #pragma unroll
    for (int d = 0; d < 64; d++) acc[d] = 0.f;
    for (int e = 0; e < 64; e++) {
        float w = Wout[(size_t)(h * 64 + e) * NDIM + tid];
        #pragma unroll
        for (int d = 0; d < 64; d++) acc[d] += ds[d * 64 + e] * w;
    }
    float* dst = W2 + (size_t)b * INNER * NDIM + (size_t)(h * 64) * NDIM + tid;
    #pragma unroll
    for (int d = 0; d < 64; d++) dst[(size_t)d * NDIM] = acc[d];
}

// ---------------- launch ----------------
extern "C" void kernel_launch(void* const* d_in, const int* in_sizes, int n_in,
                              void* d_out, int out_size) {
    const float* x     = (const float*)d_in[0];
    const float* z     = (const float*)d_in[1];
    const float* x_pos = (const float*)d_in[2];
    const float* z_pos = (const float*)d_in[3];
    const float* Wq    = (const float*)d_in[4];
    const float* Wkv   = (const float*)d_in[5];
    const float* Wout  = (const float*)d_in[6];
    const float* bout  = (const float*)d_in[7];
    float* out = (float*)d_out;

    float *kv, *q, *dotp, *w2;
    cudaGetSymbolAddress((void**)&kv,   g_kv);
    cudaGetSymbolAddress((void**)&q,    g_q);
    cudaGetSymbolAddress((void**)&dotp, g_dotp);
    cudaGetSymbolAddress((void**)&w2,   g_w2);

    const int M = BATCH * NTOKS; // 32768

    // kv = z @ Wkv
    sgemm128<<<dim3(1024 / 128, M / 128, 1), 256>>>(z, Wkv, kv, M, 1024, 256, 0, 0, 0, nullptr);
    // instance norm (k,v) + rotary (k)
    normrot_kv<<<M, 256>>>(kv, z_pos);
    // dots partials (split-K over tokens)
    dots_part<<<dim3(8, 64), 256>>>(kv, dotp);
    // W2 = (dots/n2) @ Wout
    w2k<<<64, 256>>>(dotp, Wout, w2);
    // q = x @ Wq
    sgemm128<<<dim3(512 / 128, M / 128, 1), 256>>>(x, Wq, q, M, 512, 256, 0, 0, 0, nullptr);
    // rotary on q
    rot_q<<<M, 256>>>(q, x_pos);
    // out[b] = q[b] @ W2[b] + bout
    sgemm128<<<dim3(256 / 128, NTOKS / 128, BATCH), 256>>>(
        q, w2, out, NTOKS, 256, 512,
        (long)NTOKS * 512, (long)512 * 256, (long)NTOKS * 256, bout);
}

// round 2
// speedup vs baseline: 1.0020x; 1.0020x over previous
#include <cuda_runtime.h>
#include <math.h>

typedef unsigned long long u64;

#define HEADS 8
#define DH    64
#define NDIM  256
#define INNER 512
#define NTOKS 4096
#define BATCH 8

// ---------------- scratch (device globals: allocation-guard safe) ----------------
__device__ float g_kv  [(size_t)BATCH * NTOKS * 1024];   // 134 MB: [b, t, (k0..k7,v0..v7) 1024]
__device__ float g_q   [(size_t)BATCH * NTOKS * INNER];  // 67 MB:  [b, t, h*64+d]
__device__ float g_dotp[(size_t)64 * 8 * DH * DH];       // 8.4 MB: [bh, split, d*64+e]
__device__ float g_w2  [(size_t)BATCH * INNER * NDIM];   // 4 MB:   [b, h*64+d, c]

// ---------------- f32x2 packed helpers (sm_103a) ----------------
__device__ __forceinline__ u64 pack2(float x, float y) {
    u64 r; asm("mov.b64 %0, {%1,%2};" : "=l"(r) : "f"(x), "f"(y)); return r;
}
__device__ __forceinline__ u64 ffma2(u64 a, u64 b, u64 c) {
    u64 d; asm("fma.rn.f32x2 %0, %1, %2, %3;" : "=l"(d) : "l"(a), "l"(b), "l"(c)); return d;
}
__device__ __forceinline__ void unpack2(u64 v, float& x, float& y) {
    asm("mov.b64 {%0,%1}, %2;" : "=f"(x), "=f"(y) : "l"(v));
}

// ---------------- generic 128x128x8 SGEMM, f32x2 inner loop ----------------
// C[M,N] = A[M,K] @ B[K,N] (+bias), row-major, all tile dims divide exactly.
__global__ __launch_bounds__(256, 2) void sgemm128(
    const float* __restrict__ A, const float* __restrict__ B, float* __restrict__ C,
    int M, int N, int K, long sA, long sB, long sC, const float* __restrict__ bias)
{
    A += (long)blockIdx.z * sA;
    B += (long)blockIdx.z * sB;
    C += (long)blockIdx.z * sC;
    const int m0 = blockIdx.y * 128, n0 = blockIdx.x * 128;
    const int tid = threadIdx.x;
    const int ty = tid >> 4, tx = tid & 15;

    __shared__ float As[8][132];
    __shared__ float Bs[8][128];

    const int arow = tid >> 1, acol = (tid & 1) * 4;
    const int brow = tid >> 5, bcol = (tid & 31) * 4;

    const float* gA = A + (long)(m0 + arow) * K + acol;
    const float* gB = B + (long)brow * N + n0 + bcol;

    u64 acc[8][4];
    #pragma unroll
    for (int i = 0; i < 8; i++)
        #pragma unroll
        for (int j = 0; j < 4; j++) acc[i][j] = 0ull;

    const int nt = K >> 3;
    float4 pa = *(const float4*)gA;
    float4 pb = *(const float4*)gB;

    for (int t = 0; t < nt; t++) {
        As[acol + 0][arow] = pa.x;
        As[acol + 1][arow] = pa.y;
        As[acol + 2][arow] = pa.z;
        As[acol + 3][arow] = pa.w;
        *(float4*)&Bs[brow][bcol] = pb;
        __syncthreads();
        if (t + 1 < nt) {
            pa = *(const float4*)(gA + (long)(t + 1) * 8);
            pb = *(const float4*)(gB + (long)(t + 1) * 8 * N);
        }
        #pragma unroll
        for (int k = 0; k < 8; k++) {
            float4 a0 = *(const float4*)&As[k][ty * 8];
            float4 a1 = *(const float4*)&As[k][ty * 8 + 4];
            const u64* bp = (const u64*)&Bs[k][tx * 8];
            u64 b0 = bp[0], b1 = bp[1], b2 = bp[2], b3 = bp[3];
            float av[8] = {a0.x, a0.y, a0.z, a0.w, a1.x, a1.y, a1.z, a1.w};
            #pragma unroll
            for (int i = 0; i < 8; i++) {
                u64 ap = pack2(av[i], av[i]);
                acc[i][0] = ffma2(ap, b0, acc[i][0]);
                acc[i][1] = ffma2(ap, b1, acc[i][1]);
                acc[i][2] = ffma2(ap, b2, acc[i][2]);
                acc[i][3] = ffma2(ap, b3, acc[i][3]);
            }
        }
        __syncthreads();
    }

    float bv[8];
    #pragma unroll
    for (int c = 0; c < 8; c++) bv[c] = 0.f;
    if (bias) {
        #pragma unroll
        for (int c = 0; c < 8; c++) bv[c] = bias[n0 + tx * 8 + c];
    }
    #pragma unroll
    for (int i = 0; i < 8; i++) {
        float o[8];
        #pragma unroll
        for (int j = 0; j < 4; j++) unpack2(acc[i][j], o[2 * j], o[2 * j + 1]);
        #pragma unroll
        for (int c = 0; c < 8; c++) o[c] += bv[c];
        const long row = m0 + ty * 8 + i;
        *(float4*)&C[row * N + n0 + tx * 8]     = make_float4(o[0], o[1], o[2], o[3]);
        *(float4*)&C[row * N + n0 + tx * 8 + 4] = make_float4(o[4], o[5], o[6], o[7]);
    }
}

// ---------------- rotary helper ----------------
// lane l of a warp holds head-dims d=l and d=32+l. Pairs are (j, j+16) within
// each 32-wide half; angle index j = l & 15 (x-half angle for d<32, y-half for d>=32).
__device__ __forceinline__ void warp_rot(float& v0, float& v1, int l, float px, float py) {
    const int j = l & 15;
    const float invf = exp2f(-(float)j * (13.287712379549449f / 16.f)); // 10000^(-j/16)
    float sx, cx, sy, cy;
    sincosf(px * invf, &sx, &cx);
    sincosf(py * invf, &sy, &cy);
    float p0 = __shfl_xor_sync(0xffffffffu, v0, 16);
    float p1 = __shfl_xor_sync(0xffffffffu, v1, 16);
    if (l < 16) { v0 = v0 * cx - p0 * sx; v1 = v1 * cy - p1 * sy; }
    else        { v0 = v0 * cx + p0 * sx; v1 = v1 * cy + p1 * sy; }
}

__device__ __forceinline__ float warp_sum(float s) {
    #pragma unroll
    for (int o = 16; o; o >>= 1) s += __shfl_xor_sync(0xffffffffu, s, o);
    return s;
}

// ---------------- instance-norm + rotary on kv (in place) ----------------
__global__ void normrot_kv(float* __restrict__ kv, const float* __restrict__ z_pos) {
    const int tok = blockIdx.x;                 // b*4096 + t
    const int w = threadIdx.x >> 5;             // head
    const int l = threadIdx.x & 31;
    float* kb = kv + (size_t)tok * 1024 + w * 64;
    float* vb = kb + 512;
    const float px = z_pos[tok * 2 + 0] * 64.f;
    const float py = z_pos[tok * 2 + 1] * 64.f;

    // k: norm + rotary
    float k0 = kb[l], k1 = kb[l + 32];
    float mu = warp_sum(k0 + k1) * (1.f / 64.f);
    float d0 = k0 - mu, d1 = k1 - mu;
    float var = warp_sum(d0 * d0 + d1 * d1) * (1.f / 64.f);
    float inv = rsqrtf(var + 1e-5f);
    d0 *= inv; d1 *= inv;
    warp_rot(d0, d1, l, px, py);
    kb[l] = d0; kb[l + 32] = d1;

    // v: norm only
    float u0 = vb[l], u1 = vb[l + 32];
    float muv = warp_sum(u0 + u1) * (1.f / 64.f);
    float e0 = u0 - muv, e1 = u1 - muv;
    float varv = warp_sum(e0 * e0 + e1 * e1) * (1.f / 64.f);
    float invv = rsqrtf(varv + 1e-5f);
    vb[l] = e0 * invv; vb[l + 32] = e1 * invv;
}

// ---------------- rotary on q (in place) ----------------
__global__ void rot_q(float* __restrict__ q, const float* __restrict__ x_pos) {
    const int tok = blockIdx.x;
    const int w = threadIdx.x >> 5;
    const int l = threadIdx.x & 31;
    float* base = q + (size_t)tok * 512 + w * 64;
    const float px = x_pos[tok * 2 + 0] * 64.f;
    const float py = x_pos[tok * 2 + 1] * 64.f;
    float v0 = base[l], v1 = base[l + 32];
    warp_rot(v0, v1, l, px, py);
    base[l] = v0; base[l + 32] = v1;
}

// ---------------- split-K Gram: dots_part[bh, split] = sum_t k[t,:]^T v[t,:] ----------------
__global__ __launch_bounds__(256) void dots_part(const float* __restrict__ kv, float* __restrict__ part) {
    const int split = blockIdx.x;   // 0..7
    const int bh = blockIdx.y;      // 0..63
    const int b = bh >> 3, h = bh & 7;
    __shared__ float ks[64][64];
    __shared__ float vs[64][64];
    const int tid = threadIdx.x;
    const int ty = tid >> 4, tx = tid & 15;
    float acc[4][4] = {};
    const float* kvb = kv + (size_t)b * NTOKS * 1024;

    for (int c = 0; c < 8; c++) {
        const int t0 = split * 512 + c * 64;
        #pragma unroll
        for (int r = 0; r < 8; r++) {
            int f = r * 256 + tid;
            int token = f >> 5;
            int isv = (f >> 4) & 1;
            int col4 = f & 15;
            float4 val = *(const float4*)&kvb[(size_t)(t0 + token) * 1024 + isv * 512 + h * 64 + col4 * 4];
            float* dst = isv ? &vs[token][col4 * 4] : &ks[token][col4 * 4];
            *(float4*)dst = val;
        }
        __syncthreads();
        #pragma unroll 4
        for (int t = 0; t < 64; t++) {
            float4 a = *(const float4*)&ks[t][ty * 4];
            float4 v = *(const float4*)&vs[t][tx * 4];
            acc[0][0] += a.x * v.x; acc[0][1] += a.x * v.y; acc[0][2] += a.x * v.z; acc[0][3] += a.x * v.w;
            acc[1][0] += a.y * v.x; acc[1][1] += a.y * v.y; acc[1][2] += a.y * v.z; acc[1][3] += a.y * v.w;
            acc[2][0] += a.z * v.x; acc[2][1] += a.z * v.y; acc[2][2] += a.z * v.z; acc[2][3] += a.z * v.w;
            acc[3][0] += a.w * v.x; acc[3][1] += a.w * v.y; acc[3][2] += a.w * v.z; acc[3][3] += a.w * v.w;
        }
        __syncthreads();
    }
    float* dst = part + ((size_t)bh * 8 + split) * 4096;
    #pragma unroll
    for (int i = 0; i < 4; i++)
        *(float4*)&dst[(ty * 4 + i) * 64 + tx * 4] = make_float4(acc[i][0], acc[i][1], acc[i][2], acc[i][3]);
}

// ---------------- W2[b, h*64+d, c] = (sum_splits dots)/n2 @ Wout[h*64+e, c] ----------------
__global__ __launch_bounds__(256) void w2k(const float* __restrict__ part, const float* __restrict__ Wout,
                                           float* __restrict__ W2) {
    const int bh = blockIdx.x;
    const int b = bh >> 3, h = bh & 7;
    __shared__ float ds[4096];
    const int tid = threadIdx.x;
    #pragma unroll
    for (int j = 0; j < 16; j++) {
        int idx = j * 256 + tid;
        float s = 0.f;
        #pragma unroll
        for (int sp = 0; sp < 8; sp++) s += part[((size_t)bh * 8 + sp) * 4096 + idx];
        ds[idx] = s * (1.f / 4096.f);
    }
    __syncthreads();

    float acc[64];
    #pragma unroll
    for (int d = 0; d < 64; d++) acc[d] = 0.f;
    for (int e = 0; e < 64; e++) {
        float w = Wout[(size_t)(h * 64 + e) * NDIM + tid];
        #pragma unroll
        for (int d = 0; d < 64; d++) acc[d] += ds[d * 64 + e] * w;
    }
    float* dst = W2 + (size_t)b * INNER * NDIM + (size_t)(h * 64) * NDIM + tid;
    #pragma unroll
    for (int d = 0; d < 64; d++) dst[(size_t)d * NDIM] = acc[d];
}

// ---------------- launch ----------------
extern "C" void kernel_launch(void* const* d_in, const int* in_sizes, int n_in,
                              void* d_out, int out_size) {
    const float* x     = (const float*)d_in[0];
    const float* z     = (const float*)d_in[1];
    const float* x_pos = (const float*)d_in[2];
    const float* z_pos = (const float*)d_in[3];
    const float* Wq    = (const float*)d_in[4];
    const float* Wkv   = (const float*)d_in[5];
    const float* Wout  = (const float*)d_in[6];
    const float* bout  = (const float*)d_in[7];
    float* out = (float*)d_out;

    float *kv, *q, *dotp, *w2;
    cudaGetSymbolAddress((void**)&kv,   g_kv);
    cudaGetSymbolAddress((void**)&q,    g_q);
    cudaGetSymbolAddress((void**)&dotp, g_dotp);
    cudaGetSymbolAddress((void**)&w2,   g_w2);

    const int M = BATCH * NTOKS; // 32768

    // kv = z @ Wkv
    sgemm128<<<dim3(1024 / 128, M / 128, 1), 256>>>(z, Wkv, kv, M, 1024, 256, 0, 0, 0, nullptr);
    // instance norm (k,v) + rotary (k)
    normrot_kv<<<M, 256>>>(kv, z_pos);
    // dots partials (split-K over tokens)
    dots_part<<<dim3(8, 64), 256>>>(kv, dotp);
    // W2 = (dots/n2) @ Wout
    w2k<<<64, 256>>>(dotp, Wout, w2);
    // q = x @ Wq
    sgemm128<<<dim3(512 / 128, M / 128, 1), 256>>>(x, Wq, q, M, 512, 256, 0, 0, 0, nullptr);
    // rotary on q
    rot_q<<<M, 256>>>(q, x_pos);
    // out[b] = q[b] @ W2[b] + bout
    sgemm128<<<dim3(256 / 128, NTOKS / 128, BATCH), 256>>>(
        q, w2, out, NTOKS, 256, 512,
        (long)NTOKS * 512, (long)512 * 256, (long)NTOKS * 256, bout);
}

// round 4
// speedup vs baseline: 1.5841x; 1.5809x over previous
#include <cuda_runtime.h>
#include <cuda_bf16.h>
#include <math.h>
#include <cstdint>

typedef unsigned long long u64;
typedef unsigned int u32;

#define HEADS 8
#define NDIM  256
#define INNER 512
#define NTOKS 4096
#define BATCH 8
#define MTOT  (BATCH * NTOKS)   // 32768

// ---------------- scratch (device globals: allocation-guard safe) ----------------
__device__ float g_kv  [(size_t)MTOT * 1024];        // fp32 kv post-GEMM / post-norm
__device__ float g_q   [(size_t)MTOT * INNER];       // fp32 q post-GEMM (pre-rotary)
__device__ float g_dotp[(size_t)64 * 8 * 64 * 64];   // dots split-K partials
__device__ __nv_bfloat16 g_z2  [(size_t)MTOT * 512];     // z split  [M, 2K]
__device__ __nv_bfloat16 g_x2  [(size_t)MTOT * 512];     // x split
__device__ __nv_bfloat16 g_wkv2[(size_t)1024 * 512];     // Wkv^T split [N, 2K]
__device__ __nv_bfloat16 g_wq2 [(size_t)512 * 512];      // Wq^T split
__device__ __nv_bfloat16 g_q2  [(size_t)MTOT * 1024];    // q post-rotary split [M, 2K]
__device__ __nv_bfloat16 g_w2s [(size_t)BATCH * 256 * 1024]; // W2^T split [b][N=256][2K=1024]

// ---------------- f32x2 helpers ----------------
__device__ __forceinline__ u64 pack2(float x, float y) {
    u64 r; asm("mov.b64 %0, {%1,%2};" : "=l"(r) : "f"(x), "f"(y)); return r;
}
__device__ __forceinline__ u64 ffma2(u64 a, u64 b, u64 c) {
    u64 d; asm("fma.rn.f32x2 %0, %1, %2, %3;" : "=l"(d) : "l"(a), "l"(b), "l"(c)); return d;
}
__device__ __forceinline__ void unpack2(u64 v, float& x, float& y) {
    asm("mov.b64 {%0,%1}, %2;" : "=f"(x), "=f"(y) : "l"(v));
}

// ---------------- sm_80-class MMA helpers (legal on plain sm_103) ----------------
__device__ __forceinline__ u32 smem_u32(const void* p) {
    u32 a; asm("{ .reg .u64 t; cvta.to.shared.u64 t, %1; cvt.u32.u64 %0, t; }" : "=r"(a) : "l"(p));
    return a;
}
__device__ __forceinline__ void cpa16(u32 dst, const void* src) {
    asm volatile("cp.async.cg.shared.global [%0], [%1], 16;" :: "r"(dst), "l"(src));
}
#define CP_COMMIT() asm volatile("cp.async.commit_group;" ::: "memory")
#define CP_WAIT(n)  asm volatile("cp.async.wait_group %0;" :: "n"(n) : "memory")

__device__ __forceinline__ void ldsm4(u32* r, u32 a) {
    asm volatile("ldmatrix.sync.aligned.m8n8.x4.shared.b16 {%0,%1,%2,%3}, [%4];"
        : "=r"(r[0]), "=r"(r[1]), "=r"(r[2]), "=r"(r[3]) : "r"(a));
}
__device__ __forceinline__ void ldsm2(u32* r, u32 a) {
    asm volatile("ldmatrix.sync.aligned.m8n8.x2.shared.b16 {%0,%1}, [%2];"
        : "=r"(r[0]), "=r"(r[1]) : "r"(a));
}
__device__ __forceinline__ void mma16816(float* c, const u32* a, const u32* b) {
    asm volatile("mma.sync.aligned.m16n8k16.row.col.f32.bf16.bf16.f32 "
        "{%0,%1,%2,%3}, {%4,%5,%6,%7}, {%8,%9}, {%0,%1,%2,%3};"
        : "+f"(c[0]), "+f"(c[1]), "+f"(c[2]), "+f"(c[3])
        : "r"(a[0]), "r"(a[1]), "r"(a[2]), "r"(a[3]), "r"(b[0]), "r"(b[1]));
}

// ---------------- split conversion ----------------
__device__ __forceinline__ void split1(float v, __nv_bfloat16& h, __nv_bfloat16& l) {
    h = __float2bfloat16(v);
    l = __float2bfloat16(v - __bfloat162float(h));
}

// in [R,256] fp32 -> out [R,512] bf16 (cols 0..255 hi, 256..511 lo)
__global__ void split_rows(const float* __restrict__ in, __nv_bfloat16* __restrict__ out) {
    size_t idx = (size_t)blockIdx.x * 256 + threadIdx.x;  // one float4
    size_t row = idx >> 6; int c4 = (int)(idx & 63);
    float4 v = ((const float4*)in)[idx];
    __nv_bfloat16 h0, l0, h1, l1, h2, l2, h3, l3;
    split1(v.x, h0, l0); split1(v.y, h1, l1); split1(v.z, h2, l2); split1(v.w, h3, l3);
    __nv_bfloat16* ph = out + row * 512 + c4 * 4;
    *(__nv_bfloat162*)(ph)     = __nv_bfloat162{h0, h1};
    *(__nv_bfloat162*)(ph + 2) = __nv_bfloat162{h2, h3};
    __nv_bfloat16* pl = ph + 256;
    *(__nv_bfloat162*)(pl)     = __nv_bfloat162{l0, l1};
    *(__nv_bfloat162*)(pl + 2) = __nv_bfloat162{l2, l3};
}

// W [256, N] fp32 -> out [N, 512] bf16 (transpose + split)
__global__ void split_wT(const float* __restrict__ W, __nv_bfloat16* __restrict__ out, int N) {
    int n = blockIdx.x, k = threadIdx.x;
    float v = W[(size_t)k * N + n];
    __nv_bfloat16 h, l; split1(v, h, l);
    out[(size_t)n * 512 + k]       = h;
    out[(size_t)n * 512 + 256 + k] = l;
}

// ---------------- split-bf16 HMMA GEMM ----------------
// C[M,N] = A2[M,2K] X B2[N,2K]^T with split semantics:
//   C = Ah Bh^T + Al Bh^T + Ah Bl^T   (hi = cols [0,K), lo = cols [K,2K))
// CTA tile 128x128, 8 warps (2x4) of 64x32, K consumed in 32-wide chunks over
// 3 segments, cp.async double-buffered smem, 80B row stride (conflict-free ldmatrix).
#define ROWB 80   // bytes per smem row (32 bf16 data + 8 pad)
#define TILEB (128 * ROWB)            // 10240
#define STAGEB (2 * TILEB)            // A + B per stage

__global__ __launch_bounds__(256, 2) void gemm_mma(
    const __nv_bfloat16* __restrict__ A2, const __nv_bfloat16* __restrict__ B2,
    float* __restrict__ C, int N, int K2,
    long sA, long sB, long sC, const float* __restrict__ bias)
{
    __shared__ __align__(1024) char smem[2 * STAGEB];   // 40 KB
    A2 += (size_t)blockIdx.z * sA;
    B2 += (size_t)blockIdx.z * sB;
    C  += (size_t)blockIdx.z * sC;
    const int m0 = blockIdx.y * 128, n0 = blockIdx.x * 128;
    const int tid = threadIdx.x, lane = tid & 31, wid = tid >> 5;
    const int wr = wid >> 2, wc = wid & 3;
    const u32 sb = smem_u32(smem);

    const int K = K2 >> 1;
    const int nch = K >> 5;          // 32-col chunks per segment
    const int total = 3 * nch;

    const int lrow = tid >> 1;           // 0..127
    const int lcg = (tid & 1) * 2;       // 16B-group pair {0,1} or {2,3}

    float acc[4][4][4];
    #pragma unroll
    for (int i = 0; i < 4; i++)
        #pragma unroll
        for (int j = 0; j < 4; j++)
            #pragma unroll
            for (int r = 0; r < 4; r++) acc[i][j][r] = 0.f;

    auto issue = [&](int it, int stage) {
        const int seg = it / nch;
        const int kk = (it - seg * nch) * 32;
        const int aoff = (seg == 1) ? K : 0;
        const int boff = (seg == 2) ? K : 0;
        const __nv_bfloat16* as = A2 + (size_t)(m0 + lrow) * K2 + aoff + kk + lcg * 8;
        const __nv_bfloat16* bs = B2 + (size_t)(n0 + lrow) * K2 + boff + kk + lcg * 8;
        const u32 da = sb + stage * STAGEB + lrow * ROWB + lcg * 16;
        const u32 db = da + TILEB;
        cpa16(da, as);      cpa16(da + 16, as + 8);
        cpa16(db, bs);      cpa16(db + 16, bs + 8);
        CP_COMMIT();
    };

    auto compute = [&](int stage) {
        const u32 ab = sb + stage * STAGEB;
        const u32 bb = ab + TILEB;
        #pragma unroll
        for (int kb = 0; kb < 2; kb++) {
            u32 a[4][4], b[4][2];
            #pragma unroll
            for (int mf = 0; mf < 4; mf++) {
                u32 addr = ab + (u32)(wr * 64 + mf * 16 + (lane & 15)) * ROWB
                              + kb * 32 + (lane >> 4) * 16;
                ldsm4(a[mf], addr);
            }
            #pragma unroll
            for (int nf = 0; nf < 4; nf++) {
                u32 addr = bb + (u32)(wc * 32 + nf * 8 + (lane & 7)) * ROWB
                              + kb * 32 + ((lane >> 3) & 1) * 16;
                ldsm2(b[nf], addr);
            }
            #pragma unroll
            for (int mf = 0; mf < 4; mf++)
                #pragma unroll
                for (int nf = 0; nf < 4; nf++)
                    mma16816(acc[mf][nf], a[mf], b[nf]);
        }
    };

    issue(0, 0);
    for (int i = 0; i < total; i++) {
        if (i + 1 < total) {
            issue(i + 1, (i + 1) & 1);
            CP_WAIT(1);
        } else {
            CP_WAIT(0);
        }
        __syncthreads();
        compute(i & 1);
        __syncthreads();
    }

    // epilogue: direct float2 stores
    const int rbase = m0 + wr * 64 + (lane >> 2);
    const int cbase = n0 + wc * 32 + (lane & 3) * 2;
    #pragma unroll
    for (int nf = 0; nf < 4; nf++) {
        const int c = cbase + nf * 8;
        float bx = 0.f, by = 0.f;
        if (bias) { bx = bias[c]; by = bias[c + 1]; }
        #pragma unroll
        for (int mf = 0; mf < 4; mf++) {
            const int r = rbase + mf * 16;
            float2 v0 = make_float2(acc[mf][nf][0] + bx, acc[mf][nf][1] + by);
            float2 v1 = make_float2(acc[mf][nf][2] + bx, acc[mf][nf][3] + by);
            *(float2*)&C[(size_t)r * N + c]       = v0;
            *(float2*)&C[(size_t)(r + 8) * N + c] = v1;
        }
    }
}

// ---------------- rotary helpers ----------------
__device__ __forceinline__ void warp_rot(float& v0, float& v1, int l, float px, float py) {
    const int j = l & 15;
    const float invf = exp2f(-(float)j * (13.287712379549449f / 16.f)); // 10000^(-j/16)
    float sx, cx, sy, cy;
    sincosf(px * invf, &sx, &cx);
    sincosf(py * invf, &sy, &cy);
    float p0 = __shfl_xor_sync(0xffffffffu, v0, 16);
    float p1 = __shfl_xor_sync(0xffffffffu, v1, 16);
    if (l < 16) { v0 = v0 * cx - p0 * sx; v1 = v1 * cy - p1 * sy; }
    else        { v0 = v0 * cx + p0 * sx; v1 = v1 * cy + p1 * sy; }
}
__device__ __forceinline__ float warp_sum(float s) {
    #pragma unroll
    for (int o = 16; o; o >>= 1) s += __shfl_xor_sync(0xffffffffu, s, o);
    return s;
}

// ---------------- instance-norm + rotary on kv (in place, fp32) ----------------
__global__ void normrot_kv(float* __restrict__ kv, const float* __restrict__ z_pos) {
    const int tok = blockIdx.x;
    const int w = threadIdx.x >> 5;
    const int l = threadIdx.x & 31;
    float* kb = kv + (size_t)tok * 1024 + w * 64;
    float* vb = kb + 512;
    const float px = z_pos[tok * 2 + 0] * 64.f;
    const float py = z_pos[tok * 2 + 1] * 64.f;

    float k0 = kb[l], k1 = kb[l + 32];
    float mu = warp_sum(k0 + k1) * (1.f / 64.f);
    float d0 = k0 - mu, d1 = k1 - mu;
    float var = warp_sum(d0 * d0 + d1 * d1) * (1.f / 64.f);
    float inv = rsqrtf(var + 1e-5f);
    d0 *= inv; d1 *= inv;
    warp_rot(d0, d1, l, px, py);
    kb[l] = d0; kb[l + 32] = d1;

    float u0 = vb[l], u1 = vb[l + 32];
    float muv = warp_sum(u0 + u1) * (1.f / 64.f);
    float e0 = u0 - muv, e1 = u1 - muv;
    float varv = warp_sum(e0 * e0 + e1 * e1) * (1.f / 64.f);
    float invv = rsqrtf(varv + 1e-5f);
    vb[l] = e0 * invv; vb[l + 32] = e1 * invv;
}

// ---------------- rotary on q: fp32 in -> split-bf16 out [M, 2K] ----------------
__global__ void rot_q(const float* __restrict__ q, const float* __restrict__ x_pos,
                      __nv_bfloat16* __restrict__ q2) {
    const int tok = blockIdx.x;
    const int w = threadIdx.x >> 5;
    const int l = threadIdx.x & 31;
    const float* base = q + (size_t)tok * 512 + w * 64;
    const float px = x_pos[tok * 2 + 0] * 64.f;
    const float py = x_pos[tok * 2 + 1] * 64.f;
    float v0 = base[l], v1 = base[l + 32];
    warp_rot(v0, v1, l, px, py);
    __nv_bfloat16* o = q2 + (size_t)tok * 1024;
    const int i0 = w * 64 + l, i1 = i0 + 32;
    __nv_bfloat16 h0, l0, h1, l1;
    split1(v0, h0, l0); split1(v1, h1, l1);
    o[i0] = h0; o[512 + i0] = l0;
    o[i1] = h1; o[512 + i1] = l1;
}

// ---------------- split-K Gram (f32x2): part[bh,split] = sum_t k^T v ----------------
__global__ __launch_bounds__(256) void dots_part(const float* __restrict__ kv, float* __restrict__ part) {
    const int split = blockIdx.x;   // 0..7
    const int bh = blockIdx.y;      // 0..63
    const int b = bh >> 3, h = bh & 7;
    __shared__ float ks[64][64];
    __shared__ float vs[64][64];
    const int tid = threadIdx.x;
    const int ty = tid >> 4, tx = tid & 15;
    u64 acc2[4][2];
    #pragma unroll
    for (int i = 0; i < 4; i++) { acc2[i][0] = 0ull; acc2[i][1] = 0ull; }
    const float* kvb = kv + (size_t)b * NTOKS * 1024;

    for (int c = 0; c < 8; c++) {
        const int t0 = split * 512 + c * 64;
        #pragma unroll
        for (int r = 0; r < 8; r++) {
            int f = r * 256 + tid;
            int token = f >> 5;
            int isv = (f >> 4) & 1;
            int col4 = f & 15;
            float4 val = *(const float4*)&kvb[(size_t)(t0 + token) * 1024 + isv * 512 + h * 64 + col4 * 4];
            float* dst = isv ? &vs[token][col4 * 4] : &ks[token][col4 * 4];
            *(float4*)dst = val;
        }
        __syncthreads();
        #pragma unroll 4
        for (int t = 0; t < 64; t++) {
            float4 a = *(const float4*)&ks[t][ty * 4];
            u64 v0 = *(const u64*)&vs[t][tx * 4];
            u64 v1 = *(const u64*)&vs[t][tx * 4 + 2];
            acc2[0][0] = ffma2(pack2(a.x, a.x), v0, acc2[0][0]);
            acc2[0][1] = ffma2(pack2(a.x, a.x), v1, acc2[0][1]);
            acc2[1][0] = ffma2(pack2(a.y, a.y), v0, acc2[1][0]);
            acc2[1][1] = ffma2(pack2(a.y, a.y), v1, acc2[1][1]);
            acc2[2][0] = ffma2(pack2(a.z, a.z), v0, acc2[2][0]);
            acc2[2][1] = ffma2(pack2(a.z, a.z), v1, acc2[2][1]);
            acc2[3][0] = ffma2(pack2(a.w, a.w), v0, acc2[3][0]);
            acc2[3][1] = ffma2(pack2(a.w, a.w), v1, acc2[3][1]);
        }
        __syncthreads();
    }
    float* dst = part + ((size_t)bh * 8 + split) * 4096;
    #pragma unroll
    for (int i = 0; i < 4; i++) {
        float o0, o1, o2, o3;
        unpack2(acc2[i][0], o0, o1);
        unpack2(acc2[i][1], o2, o3);
        *(float4*)&dst[(ty * 4 + i) * 64 + tx * 4] = make_float4(o0, o1, o2, o3);
    }
}

// ---------------- W2s[b][c][.] = split_bf16( ((sum dots)/n2 @ Wout)^T ) ----------------
__global__ __launch_bounds__(256) void w2k(const float* __restrict__ part, const float* __restrict__ Wout,
                                           __nv_bfloat16* __restrict__ W2s) {
    const int bh = blockIdx.x, dhalf = blockIdx.y;
    const int b = bh >> 3, h = bh & 7;
    __shared__ float ds[2048];   // [32 d_rel][64 e]
    const int tid = threadIdx.x;
    #pragma unroll
    for (int j = 0; j < 8; j++) {
        int idx = j * 256 + tid;
        int dr = idx >> 6, e = idx & 63;
        float s = 0.f;
        #pragma unroll
        for (int sp = 0; sp < 8; sp++)
            s += part[((size_t)bh * 8 + sp) * 4096 + (dhalf * 32 + dr) * 64 + e];
        ds[idx] = s * (1.f / 4096.f);
    }
    __syncthreads();

    const int p = tid & 127, g = tid >> 7;   // col pair, d-quarter
    u64 acc[16];
    #pragma unroll
    for (int d = 0; d < 16; d++) acc[d] = 0ull;
    for (int e = 0; e < 64; e++) {
        u64 w2 = *(const u64*)&Wout[(size_t)(h * 64 + e) * 256 + 2 * p];
        const float* dsr = &ds[(g * 16) * 64 + e];
        #pragma unroll
        for (int d = 0; d < 16; d++) {
            float val = dsr[d * 64];
            acc[d] = ffma2(pack2(val, val), w2, acc[d]);
        }
    }
    #pragma unroll
    for (int d = 0; d < 16; d++) {
        float o0, o1; unpack2(acc[d], o0, o1);
        const int dg = h * 64 + dhalf * 32 + g * 16 + d;
        size_t r0 = ((size_t)b * 256 + 2 * p) * 1024;
        __nv_bfloat16 hh, ll;
        split1(o0, hh, ll);
        W2s[r0 + dg] = hh; W2s[r0 + 512 + dg] = ll;
        split1(o1, hh, ll);
        W2s[r0 + 1024 + dg] = hh; W2s[r0 + 1024 + 512 + dg] = ll;
    }
}

// ---------------- launch ----------------
extern "C" void kernel_launch(void* const* d_in, const int* in_sizes, int n_in,
                              void* d_out, int out_size) {
    const float* x     = (const float*)d_in[0];
    const float* z     = (const float*)d_in[1];
    const float* x_pos = (const float*)d_in[2];
    const float* z_pos = (const float*)d_in[3];
    const float* Wq    = (const float*)d_in[4];
    const float* Wkv   = (const float*)d_in[5];
    const float* Wout  = (const float*)d_in[6];
    const float* bout  = (const float*)d_in[7];
    float* out = (float*)d_out;

    float *kv, *q, *dotp;
    __nv_bfloat16 *z2, *x2, *wkv2, *wq2, *q2, *w2s;
    cudaGetSymbolAddress((void**)&kv,   g_kv);
    cudaGetSymbolAddress((void**)&q,    g_q);
    cudaGetSymbolAddress((void**)&dotp, g_dotp);
    cudaGetSymbolAddress((void**)&z2,   g_z2);
    cudaGetSymbolAddress((void**)&x2,   g_x2);
    cudaGetSymbolAddress((void**)&wkv2, g_wkv2);
    cudaGetSymbolAddress((void**)&wq2,  g_wq2);
    cudaGetSymbolAddress((void**)&q2,   g_q2);
    cudaGetSymbolAddress((void**)&w2s,  g_w2s);

    // splits
    split_rows<<<MTOT * 64 / 256, 256>>>(z, z2);
    split_wT<<<1024, 256>>>(Wkv, wkv2, 1024);
    split_rows<<<MTOT * 64 / 256, 256>>>(x, x2);
    split_wT<<<512, 256>>>(Wq, wq2, 512);

    // kv = z @ Wkv  (M=32768, N=1024, K=256)
    gemm_mma<<<dim3(8, 256, 1), 256>>>(z2, wkv2, kv, 1024, 512, 0, 0, 0, nullptr);
    // instance norm (k,v) + rotary (k)
    normrot_kv<<<MTOT, 256>>>(kv, z_pos);
    // dots partials
    dots_part<<<dim3(8, 64), 256>>>(kv, dotp);
    // W2 = (dots/n2) @ Wout -> transposed split bf16
    w2k<<<dim3(64, 2), 256>>>(dotp, Wout, w2s);
    // q = x @ Wq  (M=32768, N=512, K=256)
    gemm_mma<<<dim3(4, 256, 1), 256>>>(x2, wq2, q, 512, 512, 0, 0, 0, nullptr);
    // rotary + split on q
    rot_q<<<MTOT, 256>>>(q, x_pos, q2);
    // out[b] = q2[b] @ W2s[b]^T + bout  (M=4096/b, N=256, K=512)
    gemm_mma<<<dim3(2, 32, BATCH), 256>>>(
        q2, w2s, out, 256, 1024,
        (long)NTOKS * 1024, (long)256 * 1024, (long)NTOKS * 256, bout);
}

// round 5
// speedup vs baseline: 1.6876x; 1.0654x over previous
#include <cuda_runtime.h>
#include <cuda_bf16.h>
#include <math.h>
#include <cstdint>

typedef unsigned long long u64;
typedef unsigned int u32;

#define HEADS 8
#define NDIM  256
#define INNER 512
#define NTOKS 4096
#define BATCH 8
#define MTOT  (BATCH * NTOKS)   // 32768

// ---------------- scratch (device globals: allocation-guard safe) ----------------
__device__ float g_kv  [(size_t)MTOT * 1024];            // fp32 kv raw GEMM output
__device__ float g_dotp[(size_t)64 * 8 * 64 * 64];       // dots split-K partials
__device__ __nv_bfloat16 g_z2  [(size_t)MTOT * 512];     // z split  [M, 2K]
__device__ __nv_bfloat16 g_x2  [(size_t)MTOT * 512];     // x split
__device__ __nv_bfloat16 g_wkv2[(size_t)1024 * 512];     // Wkv^T split [N, 2K]
__device__ __nv_bfloat16 g_wq2 [(size_t)512 * 512];      // Wq^T split
__device__ __nv_bfloat16 g_q2  [(size_t)MTOT * 1024];    // q post-rotary split [M, 2K]
__device__ __nv_bfloat16 g_w2s [(size_t)BATCH * 256 * 1024]; // W2^T split [b][256][1024]

// ---------------- f32x2 helpers ----------------
__device__ __forceinline__ u64 pack2(float x, float y) {
    u64 r; asm("mov.b64 %0, {%1,%2};" : "=l"(r) : "f"(x), "f"(y)); return r;
}
__device__ __forceinline__ u64 ffma2(u64 a, u64 b, u64 c) {
    u64 d; asm("fma.rn.f32x2 %0, %1, %2, %3;" : "=l"(d) : "l"(a), "l"(b), "l"(c)); return d;
}
__device__ __forceinline__ void unpack2(u64 v, float& x, float& y) {
    asm("mov.b64 {%0,%1}, %2;" : "=f"(x), "=f"(y) : "l"(v));
}

// ---------------- sm_80-class MMA helpers (legal on plain sm_103) ----------------
__device__ __forceinline__ u32 smem_u32(const void* p) {
    u32 a; asm("{ .reg .u64 t; cvta.to.shared.u64 t, %1; cvt.u32.u64 %0, t; }" : "=r"(a) : "l"(p));
    return a;
}
__device__ __forceinline__ void cpa16(u32 dst, const void* src) {
    asm volatile("cp.async.cg.shared.global [%0], [%1], 16;" :: "r"(dst), "l"(src));
}
#define CP_COMMIT() asm volatile("cp.async.commit_group;" ::: "memory")
#define CP_WAIT(n)  asm volatile("cp.async.wait_group %0;" :: "n"(n) : "memory")

__device__ __forceinline__ void ldsm4(u32* r, u32 a) {
    asm volatile("ldmatrix.sync.aligned.m8n8.x4.shared.b16 {%0,%1,%2,%3}, [%4];"
        : "=r"(r[0]), "=r"(r[1]), "=r"(r[2]), "=r"(r[3]) : "r"(a));
}
__device__ __forceinline__ void ldsm2(u32* r, u32 a) {
    asm volatile("ldmatrix.sync.aligned.m8n8.x2.shared.b16 {%0,%1}, [%2];"
        : "=r"(r[0]), "=r"(r[1]) : "r"(a));
}
__device__ __forceinline__ void mma16816(float* c, const u32* a, const u32* b) {
    asm volatile("mma.sync.aligned.m16n8k16.row.col.f32.bf16.bf16.f32 "
        "{%0,%1,%2,%3}, {%4,%5,%6,%7}, {%8,%9}, {%0,%1,%2,%3};"
        : "+f"(c[0]), "+f"(c[1]), "+f"(c[2]), "+f"(c[3])
        : "r"(a[0]), "r"(a[1]), "r"(a[2]), "r"(a[3]), "r"(b[0]), "r"(b[1]));
}

// ---------------- split conversion ----------------
__device__ __forceinline__ void split1(float v, __nv_bfloat16& h, __nv_bfloat16& l) {
    h = __float2bfloat16(v);
    l = __float2bfloat16(v - __bfloat162float(h));
}

// in [R,256] fp32 -> out [R,512] bf16 (cols 0..255 hi, 256..511 lo)
__global__ void split_rows(const float* __restrict__ in, __nv_bfloat16* __restrict__ out) {
    size_t idx = (size_t)blockIdx.x * 256 + threadIdx.x;  // one float4
    size_t row = idx >> 6; int c4 = (int)(idx & 63);
    float4 v = ((const float4*)in)[idx];
    __nv_bfloat16 h0, l0, h1, l1, h2, l2, h3, l3;
    split1(v.x, h0, l0); split1(v.y, h1, l1); split1(v.z, h2, l2); split1(v.w, h3, l3);
    __nv_bfloat16* ph = out + row * 512 + c4 * 4;
    *(__nv_bfloat162*)(ph)     = __nv_bfloat162{h0, h1};
    *(__nv_bfloat162*)(ph + 2) = __nv_bfloat162{h2, h3};
    __nv_bfloat16* pl = ph + 256;
    *(__nv_bfloat162*)(pl)     = __nv_bfloat162{l0, l1};
    *(__nv_bfloat162*)(pl + 2) = __nv_bfloat162{l2, l3};
}

// W [256, N] fp32 -> out [N, 512] bf16 (transpose + split)
__global__ void split_wT(const float* __restrict__ W, __nv_bfloat16* __restrict__ out, int N) {
    int n = blockIdx.x, k = threadIdx.x;
    float v = W[(size_t)k * N + n];
    __nv_bfloat16 h, l; split1(v, h, l);
    out[(size_t)n * 512 + k]       = h;
    out[(size_t)n * 512 + 256 + k] = l;
}

// ---------------- split-bf16 HMMA GEMM, 4-stage cp.async pipeline ----------------
// C[M,N] = Ah Bh^T + Al Bh^T + Ah Bl^T    (hi = cols [0,K), lo = [K,2K))
// CTA tile 128x128, 8 warps (2x4) of 64x32, 32-wide K chunks over 3 segments.
// MODE 0: fp32 C (+bias).  MODE 1: 2D-rotary + hi/lo bf16 split -> Cq [M, 2N].
#define ROWB 80                  // 32 bf16 + 16B pad
#define TILEB (128 * ROWB)       // 10240
#define STAGEB (2 * TILEB)       // 20480 (A + B)
#define NSTAGE 4
#define GSMEM (NSTAGE * STAGEB)  // 81920

template <int MODE>
__global__ __launch_bounds__(256, 2) void gemm_mma(
    const __nv_bfloat16* __restrict__ A2, const __nv_bfloat16* __restrict__ B2,
    float* __restrict__ C, __nv_bfloat16* __restrict__ Cq,
    const float* __restrict__ pos, int N, int K2,
    long sA, long sB, long sC, const float* __restrict__ bias)
{
    extern __shared__ __align__(1024) char smem[];
    A2 += (size_t)blockIdx.z * sA;
    B2 += (size_t)blockIdx.z * sB;
    if (MODE == 0) C += (size_t)blockIdx.z * sC;
    const int m0 = blockIdx.y * 128, n0 = blockIdx.x * 128;
    const int tid = threadIdx.x, lane = tid & 31, wid = tid >> 5;
    const int wr = wid >> 2, wc = wid & 3;
    const u32 sb = smem_u32(smem);

    const int K = K2 >> 1;
    const int nch = K >> 5;
    const int total = 3 * nch;

    const int lrow = tid >> 1;
    const int lcg = (tid & 1) * 2;

    float acc[4][4][4];
    #pragma unroll
    for (int i = 0; i < 4; i++)
        #pragma unroll
        for (int j = 0; j < 4; j++)
            #pragma unroll
            for (int r = 0; r < 4; r++) acc[i][j][r] = 0.f;

    auto issue = [&](int it) {
        const int stage = it & (NSTAGE - 1);
        const int seg = it / nch;
        const int kk = (it - seg * nch) * 32;
        const int aoff = (seg == 1) ? K : 0;
        const int boff = (seg == 2) ? K : 0;
        const __nv_bfloat16* as = A2 + (size_t)(m0 + lrow) * K2 + aoff + kk + lcg * 8;
        const __nv_bfloat16* bs = B2 + (size_t)(n0 + lrow) * K2 + boff + kk + lcg * 8;
        const u32 da = sb + stage * STAGEB + lrow * ROWB + lcg * 16;
        cpa16(da, as);              cpa16(da + 16, as + 8);
        cpa16(da + TILEB, bs);      cpa16(da + TILEB + 16, bs + 8);
        CP_COMMIT();
    };

    auto compute = [&](int stage) {
        const u32 ab = sb + stage * STAGEB;
        const u32 bb = ab + TILEB;
        #pragma unroll
        for (int kb = 0; kb < 2; kb++) {
            u32 a[4][4], b[4][2];
            #pragma unroll
            for (int mf = 0; mf < 4; mf++) {
                u32 addr = ab + (u32)(wr * 64 + mf * 16 + (lane & 15)) * ROWB
                              + kb * 32 + (lane >> 4) * 16;
                ldsm4(a[mf], addr);
            }
            #pragma unroll
            for (int nf = 0; nf < 4; nf++) {
                u32 addr = bb + (u32)(wc * 32 + nf * 8 + (lane & 7)) * ROWB
                              + kb * 32 + ((lane >> 3) & 1) * 16;
                ldsm2(b[nf], addr);
            }
            #pragma unroll
            for (int mf = 0; mf < 4; mf++)
                #pragma unroll
                for (int nf = 0; nf < 4; nf++)
                    mma16816(acc[mf][nf], a[mf], b[nf]);
        }
    };

    issue(0); issue(1); issue(2);
    for (int i = 0; i < total; i++) {
        if (i < total - 2)       CP_WAIT(2);
        else if (i == total - 2) CP_WAIT(1);
        else                     CP_WAIT(0);
        __syncthreads();
        compute(i & (NSTAGE - 1));
        if (i + 3 < total) issue(i + 3);
    }

    if (MODE == 0) {
        const int rbase = m0 + wr * 64 + (lane >> 2);
        const int cbase = n0 + wc * 32 + (lane & 3) * 2;
        #pragma unroll
        for (int nf = 0; nf < 4; nf++) {
            const int c = cbase + nf * 8;
            float bx = 0.f, by = 0.f;
            if (bias) { bx = bias[c]; by = bias[c + 1]; }
            #pragma unroll
            for (int mf = 0; mf < 4; mf++) {
                const int r = rbase + mf * 16;
                *(float2*)&C[(size_t)r * N + c] =
                    make_float2(acc[mf][nf][0] + bx, acc[mf][nf][1] + by);
                *(float2*)&C[(size_t)(r + 8) * N + c] =
                    make_float2(acc[mf][nf][2] + bx, acc[mf][nf][3] + by);
            }
        }
    } else {
        // rotary (pairs (j, j+16) are nf<->nf+2, thread-local) + hi/lo split store
        const int half = wc & 1;         // 0: x-angle, 1: y-angle
        const int lq = lane & 3;
        #pragma unroll
        for (int mf = 0; mf < 4; mf++) {
            #pragma unroll
            for (int rb = 0; rb < 2; rb++) {
                const int r = m0 + wr * 64 + mf * 16 + (lane >> 2) + rb * 8;
                const float pp = pos[(size_t)r * 2 + half] * 64.f;
                const size_t rowb = (size_t)r * (2 * N);
                #pragma unroll
                for (int nf2 = 0; nf2 < 2; nf2++) {
                    float o[4];
                    #pragma unroll
                    for (int cb = 0; cb < 2; cb++) {
                        const int j = nf2 * 8 + lq * 2 + cb;   // 0..15
                        const float invf = exp2f(-(float)j * (13.287712379549449f / 16.f));
                        float s, co; sincosf(pp * invf, &s, &co);
                        const int idx = rb * 2 + cb;
                        const float vlo = acc[mf][nf2][idx];
                        const float vhi = acc[mf][nf2 + 2][idx];
                        o[cb]     = vlo * co - vhi * s;   // position j
                        o[2 + cb] = vhi * co + vlo * s;   // position j+16
                    }
                    const int cg = n0 + wc * 32 + nf2 * 8 + lq * 2;
                    __nv_bfloat16 h0, l0, h1, l1;
                    split1(o[0], h0, l0); split1(o[1], h1, l1);
                    *(__nv_bfloat162*)&Cq[rowb + cg]     = __nv_bfloat162{h0, h1};
                    *(__nv_bfloat162*)&Cq[rowb + N + cg] = __nv_bfloat162{l0, l1};
                    split1(o[2], h0, l0); split1(o[3], h1, l1);
                    *(__nv_bfloat162*)&Cq[rowb + cg + 16]     = __nv_bfloat162{h0, h1};
                    *(__nv_bfloat162*)&Cq[rowb + N + cg + 16] = __nv_bfloat162{l0, l1};
                }
            }
        }
    }
}

// ---------------- rotary helpers ----------------
__device__ __forceinline__ void warp_rot(float& v0, float& v1, int l, float px, float py) {
    const int j = l & 15;
    const float invf = exp2f(-(float)j * (13.287712379549449f / 16.f)); // 10000^(-j/16)
    float sx, cx, sy, cy;
    sincosf(px * invf, &sx, &cx);
    sincosf(py * invf, &sy, &cy);
    float p0 = __shfl_xor_sync(0xffffffffu, v0, 16);
    float p1 = __shfl_xor_sync(0xffffffffu, v1, 16);
    if (l < 16) { v0 = v0 * cx - p0 * sx; v1 = v1 * cy - p1 * sy; }
    else        { v0 = v0 * cx + p0 * sx; v1 = v1 * cy + p1 * sy; }
}
__device__ __forceinline__ float warp_sum(float s) {
    #pragma unroll
    for (int o = 16; o; o >>= 1) s += __shfl_xor_sync(0xffffffffu, s, o);
    return s;
}

// ---------------- fused norm+rotary+Gram split-K: part[bh,split] = sum_t k~^T v~ ----------------
__global__ __launch_bounds__(256) void dots_fused(const float* __restrict__ kv,
                                                  const float* __restrict__ z_pos,
                                                  float* __restrict__ part) {
    const int split = blockIdx.x;   // 0..7
    const int bh = blockIdx.y;      // 0..63
    const int b = bh >> 3, h = bh & 7;
    __shared__ float ks[64][64];
    __shared__ float vs[64][64];
    const int tid = threadIdx.x;
    const int w = tid >> 5, l = tid & 31;
    const int ty = tid >> 4, tx = tid & 15;
    u64 acc2[4][2];
    #pragma unroll
    for (int i = 0; i < 4; i++) { acc2[i][0] = 0ull; acc2[i][1] = 0ull; }
    const float* kvb = kv + (size_t)b * NTOKS * 1024;

    for (int c = 0; c < 8; c++) {
        const int t0 = split * 512 + c * 64;
        #pragma unroll
        for (int r = 0; r < 8; r++) {
            int f = r * 256 + tid;
            int token = f >> 5;
            int isv = (f >> 4) & 1;
            int col4 = f & 15;
            float4 val = *(const float4*)&kvb[(size_t)(t0 + token) * 1024 + isv * 512 + h * 64 + col4 * 4];
            float* dst = isv ? &vs[token][col4 * 4] : &ks[token][col4 * 4];
            *(float4*)dst = val;
        }
        __syncthreads();
        // normalize + rotary in smem: warp w handles tokens s*8 + w
        #pragma unroll
        for (int s = 0; s < 8; s++) {
            const int t = s * 8 + w;
            float* kr = ks[t];
            float* vr = vs[t];
            float k0 = kr[l], k1 = kr[l + 32];
            float mu = warp_sum(k0 + k1) * (1.f / 64.f);
            float d0 = k0 - mu, d1 = k1 - mu;
            float var = warp_sum(d0 * d0 + d1 * d1) * (1.f / 64.f);
            float inv = rsqrtf(var + 1e-5f);
            d0 *= inv; d1 *= inv;
            const size_t tg = (size_t)b * NTOKS + t0 + t;
            const float px = z_pos[tg * 2 + 0] * 64.f;
            const float py = z_pos[tg * 2 + 1] * 64.f;
            warp_rot(d0, d1, l, px, py);
            kr[l] = d0; kr[l + 32] = d1;

            float u0 = vr[l], u1 = vr[l + 32];
            float muv = warp_sum(u0 + u1) * (1.f / 64.f);
            float e0 = u0 - muv, e1 = u1 - muv;
            float varv = warp_sum(e0 * e0 + e1 * e1) * (1.f / 64.f);
            float invv = rsqrtf(varv + 1e-5f);
            vr[l] = e0 * invv; vr[l + 32] = e1 * invv;
        }
        __syncthreads();
        #pragma unroll 4
        for (int t = 0; t < 64; t++) {
            float4 a = *(const float4*)&ks[t][ty * 4];
            u64 v0 = *(const u64*)&vs[t][tx * 4];
            u64 v1 = *(const u64*)&vs[t][tx * 4 + 2];
            acc2[0][0] = ffma2(pack2(a.x, a.x), v0, acc2[0][0]);
            acc2[0][1] = ffma2(pack2(a.x, a.x), v1, acc2[0][1]);
            acc2[1][0] = ffma2(pack2(a.y, a.y), v0, acc2[1][0]);
            acc2[1][1] = ffma2(pack2(a.y, a.y), v1, acc2[1][1]);
            acc2[2][0] = ffma2(pack2(a.z, a.z), v0, acc2[2][0]);
            acc2[2][1] = ffma2(pack2(a.z, a.z), v1, acc2[2][1]);
            acc2[3][0] = ffma2(pack2(a.w, a.w), v0, acc2[3][0]);
            acc2[3][1] = ffma2(pack2(a.w, a.w), v1, acc2[3][1]);
        }
        __syncthreads();
    }
    float* dst = part + ((size_t)bh * 8 + split) * 4096;
    #pragma unroll
    for (int i = 0; i < 4; i++) {
        float o0, o1, o2, o3;
        unpack2(acc2[i][0], o0, o1);
        unpack2(acc2[i][1], o2, o3);
        *(float4*)&dst[(ty * 4 + i) * 64 + tx * 4] = make_float4(o0, o1, o2, o3);
    }
}

// ---------------- W2s[b][c][.] = split_bf16( ((sum dots)/n2 @ Wout)^T ) ----------------
__global__ __launch_bounds__(256) void w2k(const float* __restrict__ part, const float* __restrict__ Wout,
                                           __nv_bfloat16* __restrict__ W2s) {
    const int bh = blockIdx.x, dhalf = blockIdx.y;
    const int b = bh >> 3, h = bh & 7;
    __shared__ float ds[2048];   // [32 d_rel][64 e]
    const int tid = threadIdx.x;
    #pragma unroll
    for (int j = 0; j < 8; j++) {
        int idx = j * 256 + tid;
        int dr = idx >> 6, e = idx & 63;
        float s = 0.f;
        #pragma unroll
        for (int sp = 0; sp < 8; sp++)
            s += part[((size_t)bh * 8 + sp) * 4096 + (dhalf * 32 + dr) * 64 + e];
        ds[idx] = s * (1.f / 4096.f);
    }
    __syncthreads();

    const int p = tid & 127, g = tid >> 7;
    u64 acc[16];
    #pragma unroll
    for (int d = 0; d < 16; d++) acc[d] = 0ull;
    for (int e = 0; e < 64; e++) {
        u64 w2 = *(const u64*)&Wout[(size_t)(h * 64 + e) * 256 + 2 * p];
        const float* dsr = &ds[(g * 16) * 64 + e];
        #pragma unroll
        for (int d = 0; d < 16; d++) {
            float val = dsr[d * 64];
            acc[d] = ffma2(pack2(val, val), w2, acc[d]);
        }
    }
    #pragma unroll
    for (int d = 0; d < 16; d++) {
        float o0, o1; unpack2(acc[d], o0, o1);
        const int dg = h * 64 + dhalf * 32 + g * 16 + d;
        size_t r0 = ((size_t)b * 256 + 2 * p) * 1024;
        __nv_bfloat16 hh, ll;
        split1(o0, hh, ll);
        W2s[r0 + dg] = hh; W2s[r0 + 512 + dg] = ll;
        split1(o1, hh, ll);
        W2s[r0 + 1024 + dg] = hh; W2s[r0 + 1024 + 512 + dg] = ll;
    }
}

// ---------------- launch ----------------
extern "C" void kernel_launch(void* const* d_in, const int* in_sizes, int n_in,
                              void* d_out, int out_size) {
    const float* x     = (const float*)d_in[0];
    const float* z     = (const float*)d_in[1];
    const float* x_pos = (const float*)d_in[2];
    const float* z_pos = (const float*)d_in[3];
    const float* Wq    = (const float*)d_in[4];
    const float* Wkv   = (const float*)d_in[5];
    const float* Wout  = (const float*)d_in[6];
    const float* bout  = (const float*)d_in[7];
    float* out = (float*)d_out;

    float *kv, *dotp;
    __nv_bfloat16 *z2, *x2, *wkv2, *wq2, *q2, *w2s;
    cudaGetSymbolAddress((void**)&kv,   g_kv);
    cudaGetSymbolAddress((void**)&dotp, g_dotp);
    cudaGetSymbolAddress((void**)&z2,   g_z2);
    cudaGetSymbolAddress((void**)&x2,   g_x2);
    cudaGetSymbolAddress((void**)&wkv2, g_wkv2);
    cudaGetSymbolAddress((void**)&wq2,  g_wq2);
    cudaGetSymbolAddress((void**)&q2,   g_q2);
    cudaGetSymbolAddress((void**)&w2s,  g_w2s);

    cudaFuncSetAttribute(gemm_mma<0>, cudaFuncAttributeMaxDynamicSharedMemorySize, GSMEM);
    cudaFuncSetAttribute(gemm_mma<1>, cudaFuncAttributeMaxDynamicSharedMemorySize, GSMEM);

    // kv chain
    split_rows<<<MTOT * 64 / 256, 256>>>(z, z2);
    split_wT<<<1024, 256>>>(Wkv, wkv2, 1024);
    gemm_mma<0><<<dim3(8, 256, 1), 256, GSMEM>>>(z2, wkv2, kv, nullptr, nullptr,
                                                 1024, 512, 0, 0, 0, nullptr);
    dots_fused<<<dim3(8, 64), 256>>>(kv, z_pos, dotp);
    w2k<<<dim3(64, 2), 256>>>(dotp, Wout, w2s);

    // q chain (rotary + split fused into epilogue)
    split_rows<<<MTOT * 64 / 256, 256>>>(x, x2);
    split_wT<<<512, 256>>>(Wq, wq2, 512);
    gemm_mma<1><<<dim3(4, 256, 1), 256, GSMEM>>>(x2, wq2, nullptr, q2, x_pos,
                                                 512, 512, 0, 0, 0, nullptr);

    // out[b] = q2[b] @ W2s[b]^T + bout
    gemm_mma<0><<<dim3(2, 32, BATCH), 256, GSMEM>>>(
        q2, w2s, out, nullptr, nullptr, 256, 1024,
        (long)NTOKS * 1024, (long)256 * 1024, (long)NTOKS * 256, bout);
}

// round 6
// speedup vs baseline: 1.6914x; 1.0023x over previous
#include <cuda_runtime.h>
#include <cuda_bf16.h>
#include <math.h>
#include <cstdint>

typedef unsigned long long u64;
typedef unsigned int u32;

#define HEADS 8
#define NDIM  256
#define INNER 512
#define NTOKS 4096
#define BATCH 8
#define MTOT  (BATCH * NTOKS)   // 32768

// ---------------- scratch (device globals: allocation-guard safe) ----------------
__device__ float g_kv  [(size_t)MTOT * 1024];            // fp32 kv raw GEMM output
__device__ float g_dotp[(size_t)64 * 8 * 64 * 64];       // dots split-K partials
__device__ __nv_bfloat16 g_z2  [(size_t)MTOT * 512];     // z split  [M, 2K]
__device__ __nv_bfloat16 g_x2  [(size_t)MTOT * 512];     // x split
__device__ __nv_bfloat16 g_wkv2[(size_t)1024 * 512];     // Wkv^T split [N, 2K]
__device__ __nv_bfloat16 g_wq2 [(size_t)512 * 512];      // Wq^T split
__device__ __nv_bfloat16 g_q2  [(size_t)MTOT * 1024];    // q post-rotary split [M, 2K]
__device__ __nv_bfloat16 g_w2s [(size_t)BATCH * 256 * 1024]; // W2^T split [b][256][1024]

// ---------------- sm_80-class MMA helpers (legal on plain sm_103) ----------------
__device__ __forceinline__ u32 smem_u32(const void* p) {
    u32 a; asm("{ .reg .u64 t; cvta.to.shared.u64 t, %1; cvt.u32.u64 %0, t; }" : "=r"(a) : "l"(p));
    return a;
}
__device__ __forceinline__ void cpa16(u32 dst, const void* src) {
    asm volatile("cp.async.cg.shared.global [%0], [%1], 16;" :: "r"(dst), "l"(src));
}
#define CP_COMMIT() asm volatile("cp.async.commit_group;" ::: "memory")
#define CP_WAIT(n)  asm volatile("cp.async.wait_group %0;" :: "n"(n) : "memory")

__device__ __forceinline__ void ldsm4(u32* r, u32 a) {
    asm volatile("ldmatrix.sync.aligned.m8n8.x4.shared.b16 {%0,%1,%2,%3}, [%4];"
        : "=r"(r[0]), "=r"(r[1]), "=r"(r[2]), "=r"(r[3]) : "r"(a));
}
__device__ __forceinline__ void ldsm4t(u32* r, u32 a) {
    asm volatile("ldmatrix.sync.aligned.m8n8.x4.trans.shared.b16 {%0,%1,%2,%3}, [%4];"
        : "=r"(r[0]), "=r"(r[1]), "=r"(r[2]), "=r"(r[3]) : "r"(a));
}
__device__ __forceinline__ void mma16816(float* c, const u32* a, const u32* b) {
    asm volatile("mma.sync.aligned.m16n8k16.row.col.f32.bf16.bf16.f32 "
        "{%0,%1,%2,%3}, {%4,%5,%6,%7}, {%8,%9}, {%0,%1,%2,%3};"
        : "+f"(c[0]), "+f"(c[1]), "+f"(c[2]), "+f"(c[3])
        : "r"(a[0]), "r"(a[1]), "r"(a[2]), "r"(a[3]), "r"(b[0]), "r"(b[1]));
}

// ---------------- f32x2 helpers ----------------
__device__ __forceinline__ u64 pack2(float x, float y) {
    u64 r; asm("mov.b64 %0, {%1,%2};" : "=l"(r) : "f"(x), "f"(y)); return r;
}
__device__ __forceinline__ u64 ffma2(u64 a, u64 b, u64 c) {
    u64 d; asm("fma.rn.f32x2 %0, %1, %2, %3;" : "=l"(d) : "l"(a), "l"(b), "l"(c)); return d;
}
__device__ __forceinline__ void unpack2(u64 v, float& x, float& y) {
    asm("mov.b64 {%0,%1}, %2;" : "=f"(x), "=f"(y) : "l"(v));
}

// ---------------- split conversion ----------------
__device__ __forceinline__ void split1(float v, __nv_bfloat16& h, __nv_bfloat16& l) {
    h = __float2bfloat16(v);
    l = __float2bfloat16(v - __bfloat162float(h));
}

// in [R,256] fp32 -> out [R,512] bf16 (cols 0..255 hi, 256..511 lo)
__global__ void split_rows(const float* __restrict__ in, __nv_bfloat16* __restrict__ out) {
    size_t idx = (size_t)blockIdx.x * 256 + threadIdx.x;  // one float4
    size_t row = idx >> 6; int c4 = (int)(idx & 63);
    float4 v = ((const float4*)in)[idx];
    __nv_bfloat16 h0, l0, h1, l1, h2, l2, h3, l3;
    split1(v.x, h0, l0); split1(v.y, h1, l1); split1(v.z, h2, l2); split1(v.w, h3, l3);
    __nv_bfloat16* ph = out + row * 512 + c4 * 4;
    *(__nv_bfloat162*)(ph)     = __nv_bfloat162{h0, h1};
    *(__nv_bfloat162*)(ph + 2) = __nv_bfloat162{h2, h3};
    __nv_bfloat16* pl = ph + 256;
    *(__nv_bfloat162*)(pl)     = __nv_bfloat162{l0, l1};
    *(__nv_bfloat162*)(pl + 2) = __nv_bfloat162{l2, l3};
}

// W [256, N] fp32 -> out [N, 512] bf16 (transpose + split)
__global__ void split_wT(const float* __restrict__ W, __nv_bfloat16* __restrict__ out, int N) {
    int n = blockIdx.x, k = threadIdx.x;
    float v = W[(size_t)k * N + n];
    __nv_bfloat16 h, l; split1(v, h, l);
    out[(size_t)n * 512 + k]       = h;
    out[(size_t)n * 512 + 256 + k] = l;
}

// ---------------- split-bf16 HMMA GEMM, 4-stage cp.async pipeline ----------------
#define ROWB 80                  // 32 bf16 + 16B pad
#define TILEB (128 * ROWB)       // 10240
#define STAGEB (2 * TILEB)       // 20480 (A + B)
#define NSTAGE 4
#define GSMEM (NSTAGE * STAGEB)  // 81920

template <int MODE>
__global__ __launch_bounds__(256, 2) void gemm_mma(
    const __nv_bfloat16* __restrict__ A2, const __nv_bfloat16* __restrict__ B2,
    float* __restrict__ C, __nv_bfloat16* __restrict__ Cq,
    const float* __restrict__ pos, int N, int K2,
    long sA, long sB, long sC, const float* __restrict__ bias)
{
    extern __shared__ __align__(1024) char smem[];
    A2 += (size_t)blockIdx.z * sA;
    B2 += (size_t)blockIdx.z * sB;
    if (MODE == 0) C += (size_t)blockIdx.z * sC;
    const int m0 = blockIdx.y * 128, n0 = blockIdx.x * 128;
    const int tid = threadIdx.x, lane = tid & 31, wid = tid >> 5;
    const int wr = wid >> 2, wc = wid & 3;
    const u32 sb = smem_u32(smem);

    const int K = K2 >> 1;
    const int nch = K >> 5;
    const int total = 3 * nch;

    const int lrow = tid >> 1;
    const int lcg = (tid & 1) * 2;

    float acc[4][4][4];
    #pragma unroll
    for (int i = 0; i < 4; i++)
        #pragma unroll
        for (int j = 0; j < 4; j++)
            #pragma unroll
            for (int r = 0; r < 4; r++) acc[i][j][r] = 0.f;

    auto issue = [&](int it) {
        const int stage = it & (NSTAGE - 1);
        const int seg = it / nch;
        const int kk = (it - seg * nch) * 32;
        const int aoff = (seg == 1) ? K : 0;
        const int boff = (seg == 2) ? K : 0;
        const __nv_bfloat16* as = A2 + (size_t)(m0 + lrow) * K2 + aoff + kk + lcg * 8;
        const __nv_bfloat16* bs = B2 + (size_t)(n0 + lrow) * K2 + boff + kk + lcg * 8;
        const u32 da = sb + stage * STAGEB + lrow * ROWB + lcg * 16;
        cpa16(da, as);              cpa16(da + 16, as + 8);
        cpa16(da + TILEB, bs);      cpa16(da + TILEB + 16, bs + 8);
        CP_COMMIT();
    };

    auto compute = [&](int stage) {
        const u32 ab = sb + stage * STAGEB;
        const u32 bb = ab + TILEB;
        #pragma unroll
        for (int kb = 0; kb < 2; kb++) {
            u32 a[4][4], b[2][4];
            #pragma unroll
            for (int mf = 0; mf < 4; mf++) {
                u32 addr = ab + (u32)(wr * 64 + mf * 16 + (lane & 15)) * ROWB
                              + kb * 32 + (lane >> 4) * 16;
                ldsm4(a[mf], addr);
            }
            #pragma unroll
            for (int nfp = 0; nfp < 2; nfp++) {
                u32 addr = bb + (u32)(wc * 32 + nfp * 16 + ((lane >> 4) << 3) + (lane & 7)) * ROWB
                              + kb * 32 + ((lane >> 3) & 1) * 16;
                ldsm4(b[nfp], addr);
            }
            #pragma unroll
            for (int mf = 0; mf < 4; mf++)
                #pragma unroll
                for (int nf = 0; nf < 4; nf++)
                    mma16816(acc[mf][nf], a[mf], &b[nf >> 1][(nf & 1) * 2]);
        }
    };

    issue(0); issue(1); issue(2);
    for (int i = 0; i < total; i++) {
        if (i < total - 2)       CP_WAIT(2);
        else if (i == total - 2) CP_WAIT(1);
        else                     CP_WAIT(0);
        __syncthreads();
        compute(i & (NSTAGE - 1));
        if (i + 3 < total) issue(i + 3);
    }

    if (MODE == 0) {
        const int rbase = m0 + wr * 64 + (lane >> 2);
        const int cbase = n0 + wc * 32 + (lane & 3) * 2;
        #pragma unroll
        for (int nf = 0; nf < 4; nf++) {
            const int c = cbase + nf * 8;
            float bx = 0.f, by = 0.f;
            if (bias) { bx = bias[c]; by = bias[c + 1]; }
            #pragma unroll
            for (int mf = 0; mf < 4; mf++) {
                const int r = rbase + mf * 16;
                *(float2*)&C[(size_t)r * N + c] =
                    make_float2(acc[mf][nf][0] + bx, acc[mf][nf][1] + by);
                *(float2*)&C[(size_t)(r + 8) * N + c] =
                    make_float2(acc[mf][nf][2] + bx, acc[mf][nf][3] + by);
            }
        }
    } else {
        const int half = wc & 1;
        const int lq = lane & 3;
        #pragma unroll
        for (int mf = 0; mf < 4; mf++) {
            #pragma unroll
            for (int rb = 0; rb < 2; rb++) {
                const int r = m0 + wr * 64 + mf * 16 + (lane >> 2) + rb * 8;
                const float pp = pos[(size_t)r * 2 + half] * 64.f;
                const size_t rowb = (size_t)r * (2 * N);
                #pragma unroll
                for (int nf2 = 0; nf2 < 2; nf2++) {
                    float o[4];
                    #pragma unroll
                    for (int cb = 0; cb < 2; cb++) {
                        const int j = nf2 * 8 + lq * 2 + cb;
                        const float invf = exp2f(-(float)j * (13.287712379549449f / 16.f));
                        float s, co; sincosf(pp * invf, &s, &co);
                        const int idx = rb * 2 + cb;
                        const float vlo = acc[mf][nf2][idx];
                        const float vhi = acc[mf][nf2 + 2][idx];
                        o[cb]     = vlo * co - vhi * s;
                        o[2 + cb] = vhi * co + vlo * s;
                    }
                    const int cg = n0 + wc * 32 + nf2 * 8 + lq * 2;
                    __nv_bfloat16 h0, l0, h1, l1;
                    split1(o[0], h0, l0); split1(o[1], h1, l1);
                    *(__nv_bfloat162*)&Cq[rowb + cg]     = __nv_bfloat162{h0, h1};
                    *(__nv_bfloat162*)&Cq[rowb + N + cg] = __nv_bfloat162{l0, l1};
                    split1(o[2], h0, l0); split1(o[3], h1, l1);
                    *(__nv_bfloat162*)&Cq[rowb + cg + 16]     = __nv_bfloat162{h0, h1};
                    *(__nv_bfloat162*)&Cq[rowb + N + cg + 16] = __nv_bfloat162{l0, l1};
                }
            }
        }
    }
}

// ---------------- rotary helpers ----------------
__device__ __forceinline__ void warp_rot(float& v0, float& v1, int l, float px, float py) {
    const int j = l & 15;
    const float invf = exp2f(-(float)j * (13.287712379549449f / 16.f));
    float sx, cx, sy, cy;
    sincosf(px * invf, &sx, &cx);
    sincosf(py * invf, &sy, &cy);
    float p0 = __shfl_xor_sync(0xffffffffu, v0, 16);
    float p1 = __shfl_xor_sync(0xffffffffu, v1, 16);
    if (l < 16) { v0 = v0 * cx - p0 * sx; v1 = v1 * cy - p1 * sy; }
    else        { v0 = v0 * cx + p0 * sx; v1 = v1 * cy + p1 * sy; }
}
__device__ __forceinline__ float warp_sum(float s) {
    #pragma unroll
    for (int o = 16; o; o >>= 1) s += __shfl_xor_sync(0xffffffffu, s, o);
    return s;
}

// ---------------- fused norm+rotary+Gram split-K, HMMA inner product ----------------
// smem layout (dynamic, 69632 B):
//   [0:16384)      ks fp32 [64][64]
//   [16384:32768)  vs fp32 [64][64]
//   [32768:41984)  kh bf16 [64][72]
//   [41984:51200)  kl bf16 [64][72]
//   [51200:60416)  vh bf16 [64][72]
//   [60416:69632)  vl bf16 [64][72]
#define DSM_BYTES 69632

__global__ __launch_bounds__(256, 2) void dots_fused(const float* __restrict__ kv,
                                                     const float* __restrict__ z_pos,
                                                     float* __restrict__ part) {
    extern __shared__ __align__(1024) char dsm[];
    float* ks = (float*)dsm;
    float* vs = (float*)(dsm + 16384);
    __nv_bfloat16* kh = (__nv_bfloat16*)(dsm + 32768);
    __nv_bfloat16* kl = (__nv_bfloat16*)(dsm + 41984);
    __nv_bfloat16* vh = (__nv_bfloat16*)(dsm + 51200);
    __nv_bfloat16* vl = (__nv_bfloat16*)(dsm + 60416);
    const u32 khb = smem_u32(kh), klb = smem_u32(kl);
    const u32 vhb = smem_u32(vh), vlb = smem_u32(vl);

    const int split = blockIdx.x;   // 0..7
    const int bh = blockIdx.y;      // 0..63
    const int b = bh >> 3, h = bh & 7;
    const int tid = threadIdx.x;
    const int w = tid >> 5, lane = tid & 31;
    const int wr = w >> 1, wc = w & 1;     // D strip: rows wr*16, cols wc*32
    const float* kvb = kv + (size_t)b * NTOKS * 1024;

    float acc[4][4];
    #pragma unroll
    for (int i = 0; i < 4; i++)
        #pragma unroll
        for (int j = 0; j < 4; j++) acc[i][j] = 0.f;

    for (int c = 0; c < 8; c++) {
        const int t0 = split * 512 + c * 64;
        // load 64 tokens x 64 dims of k and v (fp32)
        #pragma unroll
        for (int r = 0; r < 8; r++) {
            int f = r * 256 + tid;
            int token = f >> 5;
            int isv = (f >> 4) & 1;
            int col4 = f & 15;
            float4 val = *(const float4*)&kvb[(size_t)(t0 + token) * 1024 + isv * 512 + h * 64 + col4 * 4];
            float* dst = isv ? &vs[token * 64 + col4 * 4] : &ks[token * 64 + col4 * 4];
            *(float4*)dst = val;
        }
        __syncthreads();
        // norm + rotary in place: warp w handles tokens s*8 + w
        #pragma unroll
        for (int s = 0; s < 8; s++) {
            const int t = s * 8 + w;
            float* kr = &ks[t * 64];
            float* vr = &vs[t * 64];
            float k0 = kr[lane], k1 = kr[lane + 32];
            float mu = warp_sum(k0 + k1) * (1.f / 64.f);
            float d0 = k0 - mu, d1 = k1 - mu;
            float var = warp_sum(d0 * d0 + d1 * d1) * (1.f / 64.f);
            float inv = rsqrtf(var + 1e-5f);
            d0 *= inv; d1 *= inv;
            const size_t tg = (size_t)b * NTOKS + t0 + t;
            const float px = z_pos[tg * 2 + 0] * 64.f;
            const float py = z_pos[tg * 2 + 1] * 64.f;
            warp_rot(d0, d1, lane, px, py);
            kr[lane] = d0; kr[lane + 32] = d1;

            float u0 = vr[lane], u1 = vr[lane + 32];
            float muv = warp_sum(u0 + u1) * (1.f / 64.f);
            float e0 = u0 - muv, e1 = u1 - muv;
            float varv = warp_sum(e0 * e0 + e1 * e1) * (1.f / 64.f);
            float invv = rsqrtf(varv + 1e-5f);
            vr[lane] = e0 * invv; vr[lane + 32] = e1 * invv;
        }
        __syncthreads();
        // convert fp32 -> split bf16 (row stride 72)
        {
            const int row = tid >> 2, cg = (tid & 3) * 16;
            #pragma unroll
            for (int i = 0; i < 4; i++) {
                float4 kvv = *(const float4*)&ks[row * 64 + cg + i * 4];
                __nv_bfloat16 h0, l0, h1, l1, h2, l2, h3, l3;
                split1(kvv.x, h0, l0); split1(kvv.y, h1, l1);
                split1(kvv.z, h2, l2); split1(kvv.w, h3, l3);
                *(__nv_bfloat162*)&kh[row * 72 + cg + i * 4]     = __nv_bfloat162{h0, h1};
                *(__nv_bfloat162*)&kh[row * 72 + cg + i * 4 + 2] = __nv_bfloat162{h2, h3};
                *(__nv_bfloat162*)&kl[row * 72 + cg + i * 4]     = __nv_bfloat162{l0, l1};
                *(__nv_bfloat162*)&kl[row * 72 + cg + i * 4 + 2] = __nv_bfloat162{l2, l3};
                float4 vvv = *(const float4*)&vs[row * 64 + cg + i * 4];
                split1(vvv.x, h0, l0); split1(vvv.y, h1, l1);
                split1(vvv.z, h2, l2); split1(vvv.w, h3, l3);
                *(__nv_bfloat162*)&vh[row * 72 + cg + i * 4]     = __nv_bfloat162{h0, h1};
                *(__nv_bfloat162*)&vh[row * 72 + cg + i * 4 + 2] = __nv_bfloat162{h2, h3};
                *(__nv_bfloat162*)&vl[row * 72 + cg + i * 4]     = __nv_bfloat162{l0, l1};
                *(__nv_bfloat162*)&vl[row * 72 + cg + i * 4 + 2] = __nv_bfloat162{l2, l3};
            }
        }
        __syncthreads();
        // HMMA: D[64,64] += k~^T v~ over 64 tokens, split-bf16 3-term
        #pragma unroll
        for (int kt = 0; kt < 4; kt++) {
            // A = k^T (m=d, k=t) via x4.trans from [t][d] tiles
            const u32 arow = (u32)(kt * 16 + (lane & 7) + ((lane >> 4) << 3));
            const u32 acol = (u32)(wr * 16 + ((lane >> 3) & 1) * 8);
            const u32 aoff = arow * 144 + acol * 2;
            u32 ah[4], al[4];
            ldsm4t(ah, khb + aoff);
            ldsm4t(al, klb + aoff);
            // B = v (k=t, n=e) via x4.trans: frags {r0,r1}=e-block0, {r2,r3}=e-block1
            const u32 brow = (u32)(kt * 16 + (lane & 7) + ((lane >> 3) & 1) * 8);
            const u32 bcol = (u32)(wc * 32 + ((lane >> 4) << 3));
            const u32 boff = brow * 144 + bcol * 2;
            u32 bh0[4], bl0[4], bh1[4], bl1[4];
            ldsm4t(bh0, vhb + boff);
            ldsm4t(bl0, vlb + boff);
            ldsm4t(bh1, vhb + boff + 32);
            ldsm4t(bl1, vlb + boff + 32);
            mma16816(acc[0], ah, &bh0[0]); mma16816(acc[0], al, &bh0[0]); mma16816(acc[0], ah, &bl0[0]);
            mma16816(acc[1], ah, &bh0[2]); mma16816(acc[1], al, &bh0[2]); mma16816(acc[1], ah, &bl0[2]);
            mma16816(acc[2], ah, &bh1[0]); mma16816(acc[2], al, &bh1[0]); mma16816(acc[2], ah, &bl1[0]);
            mma16816(acc[3], ah, &bh1[2]); mma16816(acc[3], al, &bh1[2]); mma16816(acc[3], ah, &bl1[2]);
        }
        __syncthreads();
    }

    // store D fragment to part[bh][split][d*64+e]
    float* dst = part + ((size_t)bh * 8 + split) * 4096;
    const int dr = wr * 16 + (lane >> 2);
    const int ec = wc * 32 + (lane & 3) * 2;
    #pragma unroll
    for (int nf = 0; nf < 4; nf++) {
        *(float2*)&dst[(size_t)dr * 64 + ec + nf * 8]       = make_float2(acc[nf][0], acc[nf][1]);
        *(float2*)&dst[(size_t)(dr + 8) * 64 + ec + nf * 8] = make_float2(acc[nf][2], acc[nf][3]);
    }
}

// ---------------- W2s[b][c][.] = split_bf16( ((sum dots)/n2 @ Wout)^T ) ----------------
__global__ __launch_bounds__(256) void w2k(const float* __restrict__ part, const float* __restrict__ Wout,
                                           __nv_bfloat16* __restrict__ W2s) {
    const int bh = blockIdx.x, dhalf = blockIdx.y;
    const int b = bh >> 3, h = bh & 7;
    __shared__ float ds[2048];   // [32 d_rel][64 e]
    const int tid = threadIdx.x;
    #pragma unroll
    for (int j = 0; j < 8; j++) {
        int idx = j * 256 + tid;
        int dr = idx >> 6, e = idx & 63;
        float s = 0.f;
        #pragma unroll
        for (int sp = 0; sp < 8; sp++)
            s += part[((size_t)bh * 8 + sp) * 4096 + (dhalf * 32 + dr) * 64 + e];
        ds[idx] = s * (1.f / 4096.f);
    }
    __syncthreads();

    const int p = tid & 127, g = tid >> 7;
    u64 acc[16];
    #pragma unroll
    for (int d = 0; d < 16; d++) acc[d] = 0ull;
    for (int e = 0; e < 64; e++) {
        u64 w2 = *(const u64*)&Wout[(size_t)(h * 64 + e) * 256 + 2 * p];
        const float* dsr = &ds[(g * 16) * 64 + e];
        #pragma unroll
        for (int d = 0; d < 16; d++) {
            float val = dsr[d * 64];
            acc[d] = ffma2(pack2(val, val), w2, acc[d]);
        }
    }
    #pragma unroll
    for (int d = 0; d < 16; d++) {
        float o0, o1; unpack2(acc[d], o0, o1);
        const int dg = h * 64 + dhalf * 32 + g * 16 + d;
        size_t r0 = ((size_t)b * 256 + 2 * p) * 1024;
        __nv_bfloat16 hh, ll;
        split1(o0, hh, ll);
        W2s[r0 + dg] = hh; W2s[r0 + 512 + dg] = ll;
        split1(o1, hh, ll);
        W2s[r0 + 1024 + dg] = hh; W2s[r0 + 1024 + 512 + dg] = ll;
    }
}

// ---------------- launch ----------------
extern "C" void kernel_launch(void* const* d_in, const int* in_sizes, int n_in,
                              void* d_out, int out_size) {
    const float* x     = (const float*)d_in[0];
    const float* z     = (const float*)d_in[1];
    const float* x_pos = (const float*)d_in[2];
    const float* z_pos = (const float*)d_in[3];
    const float* Wq    = (const float*)d_in[4];
    const float* Wkv   = (const float*)d_in[5];
    const float* Wout  = (const float*)d_in[6];
    const float* bout  = (const float*)d_in[7];
    float* out = (float*)d_out;

    float *kv, *dotp;
    __nv_bfloat16 *z2, *x2, *wkv2, *wq2, *q2, *w2s;
    cudaGetSymbolAddress((void**)&kv,   g_kv);
    cudaGetSymbolAddress((void**)&dotp, g_dotp);
    cudaGetSymbolAddress((void**)&z2,   g_z2);
    cudaGetSymbolAddress((void**)&x2,   g_x2);
    cudaGetSymbolAddress((void**)&wkv2, g_wkv2);
    cudaGetSymbolAddress((void**)&wq2,  g_wq2);
    cudaGetSymbolAddress((void**)&q2,   g_q2);
    cudaGetSymbolAddress((void**)&w2s,  g_w2s);

    cudaFuncSetAttribute(gemm_mma<0>, cudaFuncAttributeMaxDynamicSharedMemorySize, GSMEM);
    cudaFuncSetAttribute(gemm_mma<1>, cudaFuncAttributeMaxDynamicSharedMemorySize, GSMEM);
    cudaFuncSetAttribute(dots_fused,  cudaFuncAttributeMaxDynamicSharedMemorySize, DSM_BYTES);

    // kv chain
    split_rows<<<MTOT * 64 / 256, 256>>>(z, z2);
    split_wT<<<1024, 256>>>(Wkv, wkv2, 1024);
    gemm_mma<0><<<dim3(8, 256, 1), 256, GSMEM>>>(z2, wkv2, kv, nullptr, nullptr,
                                                 1024, 512, 0, 0, 0, nullptr);
    dots_fused<<<dim3(8, 64), 256, DSM_BYTES>>>(kv, z_pos, dotp);
    w2k<<<dim3(64, 2), 256>>>(dotp, Wout, w2s);

    // q chain (rotary + split fused into epilogue)
    split_rows<<<MTOT * 64 / 256, 256>>>(x, x2);
    split_wT<<<512, 256>>>(Wq, wq2, 512);
    gemm_mma<1><<<dim3(4, 256, 1), 256, GSMEM>>>(x2, wq2, nullptr, q2, x_pos,
                                                 512, 512, 0, 0, 0, nullptr);

    // out[b] = q2[b] @ W2s[b]^T + bout
    gemm_mma<0><<<dim3(2, 32, BATCH), 256, GSMEM>>>(
        q2, w2s, out, nullptr, nullptr, 256, 1024,
        (long)NTOKS * 1024, (long)256 * 1024, (long)NTOKS * 256, bout);
}